// round 1
// baseline (speedup 1.0000x reference)
#include <cuda_runtime.h>
#include <math.h>

#define N_TABLES 26
#define ROWS 100001
#define D 64
#define BATCH 8192
#define L 4
#define NFEAT 27            // 1 dense + 26 embedding features
#define FEAT_LD (NFEAT * D) // 1728
#define NPAIR 351           // 27*26/2
#define RWIDTH 415          // 64 + 351

// ---------------- scratch (device globals; no runtime allocation) -----------
__device__ float g_b0[BATCH * 512];
__device__ float g_b1[BATCH * 256];
__device__ float g_feat[BATCH * FEAT_LD];   // [b][feat][d], feat 0 = bottom-MLP x
__device__ float g_R[BATCH * RWIDTH];
__device__ float g_t0[BATCH * 512];
__device__ float g_t1[BATCH * 256];

// ---------------- generic fused GEMM: C = act(A[M,K] * W[N,K]^T + bias) -----
// BM=BN=64, BK=16, 256 threads, 4x4 per-thread micro-tile.
__global__ void __launch_bounds__(256)
gemm_bias_act(const float* __restrict__ A, int lda,
              const float* __restrict__ W,        // [N,K] row-major
              const float* __restrict__ bias,
              float* __restrict__ C, int ldc,
              int M, int N, int K, int do_relu)
{
    __shared__ float As[16][64];
    __shared__ float Ws[16][64];

    const int tid = threadIdx.x;
    const int tx = tid & 15;        // 0..15 -> 4 output cols
    const int ty = tid >> 4;        // 0..15 -> 4 output rows
    const int bm = blockIdx.y * 64;
    const int bn = blockIdx.x * 64;

    const int lr = tid >> 2;        // 0..63  row within tile (load)
    const int lk = (tid & 3) * 4;   // 0,4,8,12

    float acc[4][4];
#pragma unroll
    for (int i = 0; i < 4; i++)
#pragma unroll
        for (int j = 0; j < 4; j++) acc[i][j] = 0.f;

    for (int k0 = 0; k0 < K; k0 += 16) {
        // load A tile (64 x 16) transposed into As[k][row]
#pragma unroll
        for (int u = 0; u < 4; u++) {
            int k = k0 + lk + u;
            As[lk + u][lr] = (k < K) ? A[(size_t)(bm + lr) * lda + k] : 0.f;
        }
        // load W tile (64 x 16) transposed into Ws[k][col]
#pragma unroll
        for (int u = 0; u < 4; u++) {
            int k = k0 + lk + u;
            Ws[lk + u][lr] = (k < K) ? W[(size_t)(bn + lr) * K + k] : 0.f;
        }
        __syncthreads();

#pragma unroll
        for (int kk = 0; kk < 16; kk++) {
            float a[4], w[4];
#pragma unroll
            for (int i = 0; i < 4; i++) a[i] = As[kk][ty * 4 + i];
#pragma unroll
            for (int j = 0; j < 4; j++) w[j] = Ws[kk][tx * 4 + j];
#pragma unroll
            for (int i = 0; i < 4; i++)
#pragma unroll
                for (int j = 0; j < 4; j++) acc[i][j] += a[i] * w[j];
        }
        __syncthreads();
    }

#pragma unroll
    for (int i = 0; i < 4; i++) {
        int row = bm + ty * 4 + i;
#pragma unroll
        for (int j = 0; j < 4; j++) {
            int col = bn + tx * 4 + j;
            float v = acc[i][j] + bias[col];
            if (do_relu) v = fmaxf(v, 0.f);
            C[(size_t)row * ldc + col] = v;
        }
    }
}

// ---------------- embedding gather + mean over L=4 ---------------------------
// one warp per (table, batch) pair; 64 floats = 32 float2 lanes
__global__ void __launch_bounds__(256)
embed_mean(const float* __restrict__ tables, const int* __restrict__ lS_i,
           float* __restrict__ feat)
{
    int gw = (blockIdx.x * blockDim.x + threadIdx.x) >> 5;
    int lane = threadIdx.x & 31;
    if (gw >= N_TABLES * BATCH) return;
    int t = gw / BATCH;
    int b = gw - t * BATCH;

    const int* idx = lS_i + (size_t)t * BATCH * L + (size_t)b * L;
    const float* tab = tables + (size_t)t * ROWS * D;

    float2 acc = make_float2(0.f, 0.f);
#pragma unroll
    for (int l = 0; l < L; l++) {
        const float2* row = (const float2*)(tab + (size_t)idx[l] * D);
        float2 v = row[lane];
        acc.x += v.x;
        acc.y += v.y;
    }
    float2* out = (float2*)(feat + (size_t)b * FEAT_LD + (size_t)(1 + t) * D);
    out[lane] = make_float2(acc.x * 0.25f, acc.y * 0.25f);
}

// ---------------- pairwise interaction + build R -----------------------------
// one block per batch element; shared 27x64 tile; 351 dot products
__global__ void __launch_bounds__(128)
interact(const float* __restrict__ feat, float* __restrict__ R)
{
    __shared__ float T[FEAT_LD];
    int b = blockIdx.x;
    const float* f = feat + (size_t)b * FEAT_LD;
    for (int i = threadIdx.x; i < FEAT_LD; i += 128) T[i] = f[i];
    __syncthreads();

    float* r = R + (size_t)b * RWIDTH;
    // copy dense feature x
    for (int i = threadIdx.x; i < D; i += 128) r[i] = T[i];

    for (int p = threadIdx.x; p < NPAIR; p += 128) {
        // row-major tril(-1) pair decode: pairs before row i: i*(i-1)/2
        int i = (int)floorf((sqrtf(8.f * (float)p + 1.f) + 1.f) * 0.5f);
        while (i * (i - 1) / 2 > p) i--;
        while ((i + 1) * i / 2 <= p) i++;
        int j = p - i * (i - 1) / 2;

        const float* ti = &T[i * D];
        const float* tj = &T[j * D];
        float s = 0.f;
#pragma unroll
        for (int k = 0; k < D; k++) s += ti[k] * tj[k];
        r[D + p] = s;
    }
}

// ---------------- final layer: [8192,256] x [256] + b ------------------------
__global__ void __launch_bounds__(256)
top_final(const float* __restrict__ A, const float* __restrict__ w,
          const float* __restrict__ bias, float* __restrict__ out)
{
    __shared__ float ws[256];
    int tid = threadIdx.x;
    ws[tid] = w[tid];
    __syncthreads();

    int warp = tid >> 5, lane = tid & 31;
    int row = blockIdx.x * 8 + warp;
    const float* a = A + (size_t)row * 256;
    float s = 0.f;
#pragma unroll
    for (int k = 0; k < 8; k++) s += a[lane + k * 32] * ws[lane + k * 32];
#pragma unroll
    for (int o = 16; o > 0; o >>= 1) s += __shfl_xor_sync(0xffffffffu, s, o);
    if (lane == 0) out[row] = s + bias[0];
}

// ---------------- launch ------------------------------------------------------
extern "C" void kernel_launch(void* const* d_in, const int* in_sizes, int n_in,
                              void* d_out, int out_size)
{
    const float* dense_x = (const float*)d_in[0];
    // d_in[1] = lS_o (unused: offsets are exactly b*L)
    const int*   lS_i    = (const int*)d_in[2];
    const float* tables  = (const float*)d_in[3];
    const float* bw0 = (const float*)d_in[4];
    const float* bb0 = (const float*)d_in[5];
    const float* bw1 = (const float*)d_in[6];
    const float* bb1 = (const float*)d_in[7];
    const float* bw2 = (const float*)d_in[8];
    const float* bb2 = (const float*)d_in[9];
    const float* tw0 = (const float*)d_in[10];
    const float* tb0 = (const float*)d_in[11];
    const float* tw1 = (const float*)d_in[12];
    const float* tb1 = (const float*)d_in[13];
    const float* tw2 = (const float*)d_in[14];
    const float* tb2 = (const float*)d_in[15];
    float* out = (float*)d_out;

    float *p_b0, *p_b1, *p_feat, *p_R, *p_t0, *p_t1;
    cudaGetSymbolAddress((void**)&p_b0,   g_b0);
    cudaGetSymbolAddress((void**)&p_b1,   g_b1);
    cudaGetSymbolAddress((void**)&p_feat, g_feat);
    cudaGetSymbolAddress((void**)&p_R,    g_R);
    cudaGetSymbolAddress((void**)&p_t0,   g_t0);
    cudaGetSymbolAddress((void**)&p_t1,   g_t1);

    // bottom MLP
    gemm_bias_act<<<dim3(512 / 64, BATCH / 64), 256>>>(
        dense_x, 13, bw0, bb0, p_b0, 512, BATCH, 512, 13, 1);
    gemm_bias_act<<<dim3(256 / 64, BATCH / 64), 256>>>(
        p_b0, 512, bw1, bb1, p_b1, 256, BATCH, 256, 512, 1);
    // bot2 writes feature slot 0 of g_feat (ldc = 27*64)
    gemm_bias_act<<<dim3(1, BATCH / 64), 256>>>(
        p_b1, 256, bw2, bb2, p_feat, FEAT_LD, BATCH, 64, 256, 1);

    // embedding gather + mean  (can overlap with bottom MLP in-stream order;
    // writes disjoint columns of g_feat)
    {
        int warps = N_TABLES * BATCH;
        int blocks = (warps + 7) / 8;
        embed_mean<<<blocks, 256>>>(tables, lS_i, p_feat);
    }

    // interaction -> R
    interact<<<BATCH, 128>>>(p_feat, p_R);

    // top MLP
    gemm_bias_act<<<dim3(512 / 64, BATCH / 64), 256>>>(
        p_R, RWIDTH, tw0, tb0, p_t0, 512, BATCH, 512, RWIDTH, 1);
    gemm_bias_act<<<dim3(256 / 64, BATCH / 64), 256>>>(
        p_t0, 512, tw1, tb1, p_t1, 256, BATCH, 256, 512, 1);
    top_final<<<BATCH / 8, 256>>>(p_t1, tw2, tb2, out);
}

// round 2
// speedup vs baseline: 2.5742x; 2.5742x over previous
#include <cuda_runtime.h>
#include <math.h>
#include <stdint.h>

#define N_TABLES 26
#define ROWS 100001
#define D 64
#define BATCH 8192
#define L 4
#define NFEAT 27
#define FEAT_LD (NFEAT * D)  // 1728
#define NPAIR 351
#define RWIDTH 415

// ---------------- scratch (device globals) ----------------------------------
__device__ float g_b0[BATCH * 512];
__device__ float g_b1[BATCH * 256];
__device__ float g_feat[BATCH * FEAT_LD];
__device__ float g_R[BATCH * RWIDTH];
__device__ float g_t0[BATCH * 512];
__device__ float g_t1[BATCH * 256];

// round f32 -> tf32 (round-to-nearest) kept in a f32 container
__device__ __forceinline__ float to_tf32(float v) {
    float r;
    asm("cvt.rna.tf32.f32 %0, %1;" : "=f"(r) : "f"(v));
    return r;
}

// ---------------- tf32 tensor-core GEMM --------------------------------------
// C[M,N] = act(A[M,K] * W[N,K]^T + bias)
// BM=128, BN=64, BK=32, 256 threads = 8 warps (4 m-warps x 2 n-warps),
// warp tile 32x32 = 2x4 m16n8k8 mma tiles.
#define ASTRIDE 36
__global__ void __launch_bounds__(256)
gemm_tf32(const float* __restrict__ A, int lda,
          const float* __restrict__ W,  // [N,K] row-major
          const float* __restrict__ bias,
          float* __restrict__ C, int ldc,
          int M, int N, int K, int do_relu)
{
    __shared__ float As[128 * ASTRIDE];
    __shared__ float Bs[64 * ASTRIDE];

    const int tid = threadIdx.x;
    const int warp = tid >> 5;
    const int lane = tid & 31;
    const int wm = warp >> 1;      // 0..3
    const int wn = warp & 1;       // 0..1
    const int g = lane >> 2;       // group id 0..7
    const int c = lane & 3;        // thread-in-group 0..3
    const int bm = blockIdx.y * 128;
    const int bn = blockIdx.x * 64;

    float acc[2][4][4];
#pragma unroll
    for (int mt = 0; mt < 2; mt++)
#pragma unroll
        for (int nt = 0; nt < 4; nt++)
#pragma unroll
            for (int q = 0; q < 4; q++) acc[mt][nt][q] = 0.f;

    for (int k0 = 0; k0 < K; k0 += 32) {
        // A tile: 128 x 32 (coalesced: consecutive tid -> consecutive k)
#pragma unroll
        for (int i = 0; i < 16; i++) {
            int idx = i * 256 + tid;
            int m = idx >> 5, k = idx & 31;
            float v = (k0 + k < K) ? A[(size_t)(bm + m) * lda + k0 + k] : 0.f;
            As[m * ASTRIDE + k] = to_tf32(v);
        }
        // B tile: 64 x 32 from W[N,K]
#pragma unroll
        for (int i = 0; i < 8; i++) {
            int idx = i * 256 + tid;
            int n = idx >> 5, k = idx & 31;
            float v = (k0 + k < K) ? W[(size_t)(bn + n) * K + k0 + k] : 0.f;
            Bs[n * ASTRIDE + k] = to_tf32(v);
        }
        __syncthreads();

#pragma unroll
        for (int ks = 0; ks < 4; ks++) {
            const int kk = ks * 8;
            uint32_t a[2][4], b[4][2];
#pragma unroll
            for (int mt = 0; mt < 2; mt++) {
                int mb = wm * 32 + mt * 16;
                a[mt][0] = __float_as_uint(As[(mb + g) * ASTRIDE + kk + c]);
                a[mt][1] = __float_as_uint(As[(mb + g + 8) * ASTRIDE + kk + c]);
                a[mt][2] = __float_as_uint(As[(mb + g) * ASTRIDE + kk + c + 4]);
                a[mt][3] = __float_as_uint(As[(mb + g + 8) * ASTRIDE + kk + c + 4]);
            }
#pragma unroll
            for (int nt = 0; nt < 4; nt++) {
                int nb = wn * 32 + nt * 8;
                b[nt][0] = __float_as_uint(Bs[(nb + g) * ASTRIDE + kk + c]);
                b[nt][1] = __float_as_uint(Bs[(nb + g) * ASTRIDE + kk + c + 4]);
            }
#pragma unroll
            for (int mt = 0; mt < 2; mt++)
#pragma unroll
                for (int nt = 0; nt < 4; nt++) {
                    asm volatile(
                        "mma.sync.aligned.m16n8k8.row.col.f32.tf32.tf32.f32 "
                        "{%0,%1,%2,%3}, {%4,%5,%6,%7}, {%8,%9}, {%0,%1,%2,%3};\n"
                        : "+f"(acc[mt][nt][0]), "+f"(acc[mt][nt][1]),
                          "+f"(acc[mt][nt][2]), "+f"(acc[mt][nt][3])
                        : "r"(a[mt][0]), "r"(a[mt][1]), "r"(a[mt][2]), "r"(a[mt][3]),
                          "r"(b[nt][0]), "r"(b[nt][1]));
                }
        }
        __syncthreads();
    }

    // epilogue: c0->(r,col), c1->(r,col+1), c2->(r+8,col), c3->(r+8,col+1)
#pragma unroll
    for (int mt = 0; mt < 2; mt++) {
        int row0 = bm + wm * 32 + mt * 16 + g;
#pragma unroll
        for (int nt = 0; nt < 4; nt++) {
            int col = bn + wn * 32 + nt * 8 + c * 2;
            float b0 = bias[col], b1 = bias[col + 1];
            float v0 = acc[mt][nt][0] + b0;
            float v1 = acc[mt][nt][1] + b1;
            float v2 = acc[mt][nt][2] + b0;
            float v3 = acc[mt][nt][3] + b1;
            if (do_relu) {
                v0 = fmaxf(v0, 0.f); v1 = fmaxf(v1, 0.f);
                v2 = fmaxf(v2, 0.f); v3 = fmaxf(v3, 0.f);
            }
            *(float2*)&C[(size_t)row0 * ldc + col] = make_float2(v0, v1);
            *(float2*)&C[(size_t)(row0 + 8) * ldc + col] = make_float2(v2, v3);
        }
    }
}

// ---------------- embedding gather + mean over L=4 ---------------------------
__global__ void __launch_bounds__(256)
embed_mean(const float* __restrict__ tables, const int* __restrict__ lS_i,
           float* __restrict__ feat)
{
    int gw = (blockIdx.x * blockDim.x + threadIdx.x) >> 5;
    int lane = threadIdx.x & 31;
    if (gw >= N_TABLES * BATCH) return;
    int t = gw / BATCH;
    int b = gw - t * BATCH;

    const int* idx = lS_i + (size_t)t * BATCH * L + (size_t)b * L;
    const float* tab = tables + (size_t)t * ROWS * D;

    int i0 = idx[0], i1 = idx[1], i2 = idx[2], i3 = idx[3];
    float2 v0 = ((const float2*)(tab + (size_t)i0 * D))[lane];
    float2 v1 = ((const float2*)(tab + (size_t)i1 * D))[lane];
    float2 v2 = ((const float2*)(tab + (size_t)i2 * D))[lane];
    float2 v3 = ((const float2*)(tab + (size_t)i3 * D))[lane];

    float sx = (v0.x + v1.x) + (v2.x + v3.x);
    float sy = (v0.y + v1.y) + (v2.y + v3.y);
    float2* out = (float2*)(feat + (size_t)b * FEAT_LD + (size_t)(1 + t) * D);
    out[lane] = make_float2(sx * 0.25f, sy * 0.25f);
}

// ---------------- pairwise interaction ---------------------------------------
// stride-65 padded tile -> conflict-free LDS (bank = (i+k)%32, i distinct per lane)
#define TSTRIDE 65
__global__ void __launch_bounds__(128)
interact(const float* __restrict__ feat, float* __restrict__ R)
{
    __shared__ float T[NFEAT * TSTRIDE];
    int b = blockIdx.x;
    const float* f = feat + (size_t)b * FEAT_LD;
    for (int i = threadIdx.x; i < FEAT_LD; i += 128) {
        int fi = i >> 6, k = i & 63;
        T[fi * TSTRIDE + k] = f[i];
    }
    __syncthreads();

    float* r = R + (size_t)b * RWIDTH;
    for (int i = threadIdx.x; i < D; i += 128) r[i] = T[i];

    for (int p = threadIdx.x; p < NPAIR; p += 128) {
        int i = (int)floorf((sqrtf(8.f * (float)p + 1.f) + 1.f) * 0.5f);
        while (i * (i - 1) / 2 > p) i--;
        while ((i + 1) * i / 2 <= p) i++;
        int j = p - i * (i - 1) / 2;

        const float* ti = &T[i * TSTRIDE];
        const float* tj = &T[j * TSTRIDE];
        float s = 0.f;
#pragma unroll
        for (int k = 0; k < D; k++) s += ti[k] * tj[k];
        r[D + p] = s;
    }
}

// ---------------- final layer: [8192,256] x [256] + b ------------------------
__global__ void __launch_bounds__(256)
top_final(const float* __restrict__ A, const float* __restrict__ w,
          const float* __restrict__ bias, float* __restrict__ out)
{
    __shared__ float ws[256];
    int tid = threadIdx.x;
    ws[tid] = w[tid];
    __syncthreads();

    int warp = tid >> 5, lane = tid & 31;
    int row = blockIdx.x * 8 + warp;
    const float* a = A + (size_t)row * 256;
    float s = 0.f;
#pragma unroll
    for (int k = 0; k < 8; k++) s += a[lane + k * 32] * ws[lane + k * 32];
#pragma unroll
    for (int o = 16; o > 0; o >>= 1) s += __shfl_xor_sync(0xffffffffu, s, o);
    if (lane == 0) out[row] = s + bias[0];
}

// ---------------- launch ------------------------------------------------------
extern "C" void kernel_launch(void* const* d_in, const int* in_sizes, int n_in,
                              void* d_out, int out_size)
{
    const float* dense_x = (const float*)d_in[0];
    const int*   lS_i    = (const int*)d_in[2];
    const float* tables  = (const float*)d_in[3];
    const float* bw0 = (const float*)d_in[4];
    const float* bb0 = (const float*)d_in[5];
    const float* bw1 = (const float*)d_in[6];
    const float* bb1 = (const float*)d_in[7];
    const float* bw2 = (const float*)d_in[8];
    const float* bb2 = (const float*)d_in[9];
    const float* tw0 = (const float*)d_in[10];
    const float* tb0 = (const float*)d_in[11];
    const float* tw1 = (const float*)d_in[12];
    const float* tb1 = (const float*)d_in[13];
    const float* tw2 = (const float*)d_in[14];
    const float* tb2 = (const float*)d_in[15];
    float* out = (float*)d_out;

    float *p_b0, *p_b1, *p_feat, *p_R, *p_t0, *p_t1;
    cudaGetSymbolAddress((void**)&p_b0,   g_b0);
    cudaGetSymbolAddress((void**)&p_b1,   g_b1);
    cudaGetSymbolAddress((void**)&p_feat, g_feat);
    cudaGetSymbolAddress((void**)&p_R,    g_R);
    cudaGetSymbolAddress((void**)&p_t0,   g_t0);
    cudaGetSymbolAddress((void**)&p_t1,   g_t1);

    // embedding gather first (independent of MLP chain)
    {
        int warps = N_TABLES * BATCH;
        int blocks = (warps + 7) / 8;
        embed_mean<<<blocks, 256>>>(tables, lS_i, p_feat);
    }

    // bottom MLP
    gemm_tf32<<<dim3(512 / 64, BATCH / 128), 256>>>(
        dense_x, 13, bw0, bb0, p_b0, 512, BATCH, 512, 13, 1);
    gemm_tf32<<<dim3(256 / 64, BATCH / 128), 256>>>(
        p_b0, 512, bw1, bb1, p_b1, 256, BATCH, 256, 512, 1);
    gemm_tf32<<<dim3(1, BATCH / 128), 256>>>(
        p_b1, 256, bw2, bb2, p_feat, FEAT_LD, BATCH, 64, 256, 1);

    // interaction -> R
    interact<<<BATCH, 128>>>(p_feat, p_R);

    // top MLP
    gemm_tf32<<<dim3(512 / 64, BATCH / 128), 256>>>(
        p_R, RWIDTH, tw0, tb0, p_t0, 512, BATCH, 512, RWIDTH, 1);
    gemm_tf32<<<dim3(256 / 64, BATCH / 128), 256>>>(
        p_t0, 512, tw1, tb1, p_t1, 256, BATCH, 256, 512, 1);
    top_final<<<BATCH / 8, 256>>>(p_t1, tw2, tb2, out);
}